// round 5
// baseline (speedup 1.0000x reference)
#include <cuda_runtime.h>
#include <cstdint>
#include <cstddef>

constexpr int kB = 128, kT = 256, kI = 256, kH = 512, kO = 128;
constexpr int kFH = 4 * kH, kBH = kB * kH, kBT = kB * kT;

// Scratch
__device__ float g_xp0[(size_t)kBT * kFH];     // [t][b][4H] layer-0 input proj
// h activations in mma-fragment-interleaved layout:
// [buf][half m (64 rows)][chunk (64 k)][4096]: within chunk, element (r,k):
// idx = (((k>>3)*4 + (r>>4))*32 + (((r&7)&7)<<2 | (k&3)))*4 + ((r>>3)&1) + ((k>>2)&1)*2
__device__ float g_h1f[2][2][8][4096];
__device__ float g_h2f[2][2][8][4096];
__device__ float g_h2p[kBH];                   // plain layout of final h2 for FC
__device__ unsigned g_leaf[8 * 32];            // leaf counters, 128B apart
__device__ unsigned g_root[64];                // [0]=count, [32]=generation

constexpr int GRID = 128, NTHR = 512;

// SMEM layout (floats)
constexpr int SM_WH0 = 0;                      // 32 gate-cols x 512 k frag-interleaved
constexpr int SM_WI1 = 16384;
constexpr int SM_WH1 = 32768;
constexpr int SM_AS  = 49152;                  // A bufs: 2 x 4096 (frag order, exact)
constexpr int SM_CEX = SM_AS;                  // k-split partials [4][64][33] alias A bufs
constexpr int SM_B2  = SM_AS + 8448;           // 57600: layer-2 bias sums (32)
constexpr int SM_MB  = SM_B2 + 32;             // 57632: 4 mbarriers (32 B)
constexpr size_t SMEM_BYTES = (size_t)(SM_MB + 8) * sizeof(float);

__device__ __forceinline__ float to_tf32(float x) {
    uint32_t u;
    asm("cvt.rna.tf32.f32 %0, %1;" : "=r"(u) : "f"(x));
    return __uint_as_float(u);
}

__device__ __forceinline__ void mma_tf32(float* d, const uint32_t* a, const uint32_t* b) {
    asm volatile(
        "mma.sync.aligned.m16n8k8.row.col.f32.tf32.tf32.f32 "
        "{%0,%1,%2,%3}, {%4,%5,%6,%7}, {%8,%9}, {%0,%1,%2,%3};\n"
        : "+f"(d[0]), "+f"(d[1]), "+f"(d[2]), "+f"(d[3])
        : "r"(a[0]), "r"(a[1]), "r"(a[2]), "r"(a[3]), "r"(b[0]), "r"(b[1]));
}

__device__ __forceinline__ float sigm(float x) { return 1.0f / (1.0f + expf(-x)); }

__device__ __forceinline__ void mbar_init(uint32_t addr, uint32_t count) {
    asm volatile("mbarrier.init.shared.b64 [%0], %1;" :: "r"(addr), "r"(count) : "memory");
}
__device__ __forceinline__ void mbar_arrive(uint32_t addr) {
    asm volatile("mbarrier.arrive.shared.b64 _, [%0];" :: "r"(addr) : "memory");
}
__device__ __forceinline__ void mbar_wait(uint32_t addr, uint32_t parity) {
    asm volatile(
        "{\n\t.reg .pred P;\n\t"
        "WL_%=:\n\t"
        "mbarrier.try_wait.parity.acquire.cta.shared::cta.b64 P, [%0], %1, 0x989680;\n\t"
        "@P bra.uni WD_%=;\n\t"
        "bra.uni WL_%=;\n\t"
        "WD_%=:\n\t}"
        :: "r"(addr), "r"(parity) : "memory");
}

// =====================================================================
// Persistent fused 2-layer LSTM scan.
// CTA: mcta=c&1 -> rows [mcta*64,+64); ncta=c>>1 -> h-cols [ncta*8,+8) of both
// layers. Iter it: layer-1 step it (it<kT) + layer-2 step it-1 (it>=1).
// 16 warps: kq=w&3 (k-quarter), mw=(w>>2)&1 (32-row half), nw=(w>>3)&1.
// A staged via cp.async into 2 bufs, producer/consumer mbarrier pipeline
// (full: 512 cp.async.noinc arrivals; empty: 16 per-warp arrivals).
// =====================================================================
__global__ void __launch_bounds__(NTHR, 1) k_scan(
    const float* __restrict__ Whh0, const float* __restrict__ Wih1,
    const float* __restrict__ Whh1, const float* __restrict__ bih1,
    const float* __restrict__ bhh1)
{
    extern __shared__ float sm[];
    const int tid  = threadIdx.x;
    const int lane = tid & 31;
    const int w    = tid >> 5;
    const int kq   = w & 3;
    const int mw   = (w >> 2) & 1;
    const int nw   = (w >> 3) & 1;
    const int mcta = blockIdx.x & 1;
    const int ncta = blockIdx.x >> 1;
    const int hbase = ncta * 8;
    const int row0  = mcta * 64;
    const int grp   = blockIdx.x >> 4;   // 8 groups of 16 for 2-level barrier

    const uint32_t mbase  = (uint32_t)__cvta_generic_to_shared(sm + SM_MB);
    const uint32_t mfull0 = mbase, mfull1 = mbase + 8;
    const uint32_t mempty0 = mbase + 16, mempty1 = mbase + 24;

    if (tid == 0) {
        mbar_init(mfull0, NTHR);
        mbar_init(mfull1, NTHR);
        mbar_init(mempty0, 16);
        mbar_init(mempty1, 16);
    }

    // ---- Weight slices, fragment-interleaved ----
    for (int i = tid; i < 32 * 512; i += NTHR) {
        const int cc = i >> 9, k = i & 511;
        const int grow = (cc >> 3) * kH + hbase + (cc & 7);
        const int idx = (((k >> 3) * 4 + (cc >> 3)) * 32 + (((cc & 7) << 2) | (k & 3))) * 2
                        + ((k >> 2) & 1);
        sm[SM_WH0 + idx] = to_tf32(Whh0[grow * kH + k]);
        sm[SM_WI1 + idx] = to_tf32(Wih1[grow * kH + k]);
        sm[SM_WH1 + idx] = to_tf32(Whh1[grow * kH + k]);
    }
    if (tid < 32) {
        const int grow = (tid >> 3) * kH + hbase + (tid & 7);
        sm[SM_B2 + tid] = bih1[grow] + bhh1[grow];
    }
    __syncthreads();

    const int er = tid >> 3;     // epilogue row (0..63)
    const int ej = tid & 7;      // epilogue h-col (0..7)
    // frag index for epilogue h store (k8l = ncta&7 constant per CTA)
    const int hidx = ((((ncta & 7) * 4 + (er >> 4)) * 32 +
                      (((er & 7) << 2) | (ej & 3))) * 4) +
                     ((er >> 3) & 1) + (((ej >> 2) & 1) << 1);
    const int hchunk = ncta >> 3;

    float c1s = 0.f, c2s = 0.f;
    unsigned gen = 0;

    for (int it = 0; it <= kT; ++it) {
        const bool do1 = (it < kT);
        const bool do2 = (it >= 1);
        const float* __restrict__ h1r = &g_h1f[it & 1][mcta][0][0];
        const float* __restrict__ h2r = &g_h2f[it & 1][mcta][0][0];

        float acc1[2][2][4], acc2[2][2][4];
#pragma unroll
        for (int mi = 0; mi < 2; ++mi)
#pragma unroll
            for (int ni = 0; ni < 2; ++ni)
#pragma unroll
                for (int q = 0; q < 4; ++q) { acc1[mi][ni][q] = 0.f; acc2[mi][ni][q] = 0.f; }

        float px[4];
        if (do1) {
            const float* xpp = &g_xp0[((size_t)it * kB + row0 + er) * kFH + hbase + ej];
            px[0] = __ldg(xpp);
            px[1] = __ldg(xpp + kH);
            px[2] = __ldg(xpp + 2 * kH);
            px[3] = __ldg(xpp + 3 * kH);
        }

        auto issue_chunk = [&](int c) {
            const float* src = (c < 8) ? h1r + (size_t)c * 4096
                                       : h2r + (size_t)(c - 8) * 4096;
            float* As = sm + SM_AS + (c & 1) * 4096;
#pragma unroll
            for (int p = 0; p < 2; ++p) {
                const int off = tid * 4 + p * 2048;
                uint32_t dst = (uint32_t)__cvta_generic_to_shared(&As[off]);
                asm volatile("cp.async.cg.shared.global [%0], [%1], 16;"
                             :: "r"(dst), "l"(src + off));
            }
            const uint32_t mf = (c & 1) ? mfull1 : mfull0;
            asm volatile("cp.async.mbarrier.arrive.noinc.shared.b64 [%0];"
                         :: "r"(mf) : "memory");
        };

        // Prologue: chunks 0,1 (buffer use index n = 8*it; wait phase n-1, parity 1)
        if (it != 0) { mbar_wait(mempty0, 1); }
        issue_chunk(0);
        if (it != 0) { mbar_wait(mempty1, 1); }
        issue_chunk(1);

#pragma unroll 1
        for (int c = 0; c < 16; ++c) {
            const int b = c & 1;
            const int u = c >> 1;
            const uint32_t mf = b ? mfull1 : mfull0;
            const uint32_t me = b ? mempty1 : mempty0;
            mbar_wait(mf, (unsigned)(u & 1));

            const float* As = sm + SM_AS + b * 4096;
            const bool ph1 = (c < 8);
#pragma unroll
            for (int kl = 0; kl < 2; ++kl) {
                const int k8l = kq * 2 + kl;
                const int k8g = (c & 7) * 8 + k8l;
                uint32_t au[2][4];
#pragma unroll
                for (int mi = 0; mi < 2; ++mi) {
                    const float4 af = *(const float4*)&As[((k8l * 4 + (mw * 2 + mi)) * 32
                                                          + lane) * 4];
                    au[mi][0] = __float_as_uint(af.x);
                    au[mi][1] = __float_as_uint(af.y);
                    au[mi][2] = __float_as_uint(af.z);
                    au[mi][3] = __float_as_uint(af.w);
                }
                if (ph1) {
#pragma unroll
                    for (int ni = 0; ni < 2; ++ni) {
                        const int tile = nw * 2 + ni;
                        if (do1) {
                            const float2 bb = *(const float2*)&sm[SM_WH0 +
                                ((k8g * 4 + tile) * 32 + lane) * 2];
                            uint32_t bu[2] = { __float_as_uint(bb.x), __float_as_uint(bb.y) };
                            mma_tf32(acc1[0][ni], au[0], bu);
                            mma_tf32(acc1[1][ni], au[1], bu);
                        }
                        if (do2) {
                            const float2 bb = *(const float2*)&sm[SM_WI1 +
                                ((k8g * 4 + tile) * 32 + lane) * 2];
                            uint32_t bu[2] = { __float_as_uint(bb.x), __float_as_uint(bb.y) };
                            mma_tf32(acc2[0][ni], au[0], bu);
                            mma_tf32(acc2[1][ni], au[1], bu);
                        }
                    }
                } else if (do2) {
#pragma unroll
                    for (int ni = 0; ni < 2; ++ni) {
                        const int tile = nw * 2 + ni;
                        const float2 bb = *(const float2*)&sm[SM_WH1 +
                            ((k8g * 4 + tile) * 32 + lane) * 2];
                        uint32_t bu[2] = { __float_as_uint(bb.x), __float_as_uint(bb.y) };
                        mma_tf32(acc2[0][ni], au[0], bu);
                        mma_tf32(acc2[1][ni], au[1], bu);
                    }
                }
            }
            if (lane == 0) mbar_arrive(me);
            if (c + 2 < 16) {
                // produce use u+1 of buf b: wait empty phase (8*it+u), parity u&1
                mbar_wait(me, (unsigned)(u & 1));
                issue_chunk(c + 2);
            }
        }

        __syncthreads();   // align warps; CEX aliases A buffers

        // ---- Layer-1 epilogue ----
        if (do1) {
#pragma unroll
            for (int mi = 0; mi < 2; ++mi)
#pragma unroll
                for (int ni = 0; ni < 2; ++ni) {
                    const int r  = mw * 32 + mi * 16 + (lane >> 2);
                    const int c0 = nw * 16 + ni * 8 + (lane & 3) * 2;
                    float* cx = &sm[SM_CEX + (kq * 64 + r) * 33 + c0];
                    cx[0]          = acc1[mi][ni][0];
                    cx[1]          = acc1[mi][ni][1];
                    cx[8 * 33]     = acc1[mi][ni][2];
                    cx[8 * 33 + 1] = acc1[mi][ni][3];
                }
            __syncthreads();
            float pre[4];
#pragma unroll
            for (int g = 0; g < 4; ++g) {
                float s = px[g];
#pragma unroll
                for (int q = 0; q < 4; ++q)
                    s += sm[SM_CEX + (q * 64 + er) * 33 + g * 8 + ej];
                pre[g] = s;
            }
            const float ig = sigm(pre[0]), fg = sigm(pre[1]);
            const float gg = tanhf(pre[2]), og = sigm(pre[3]);
            const float cn = fg * c1s + ig * gg;
            c1s = cn;
            g_h1f[(it + 1) & 1][mcta][hchunk][hidx] = to_tf32(og * tanhf(cn));
        }
        __syncthreads();

        // ---- Layer-2 epilogue ----
        if (do2) {
#pragma unroll
            for (int mi = 0; mi < 2; ++mi)
#pragma unroll
                for (int ni = 0; ni < 2; ++ni) {
                    const int r  = mw * 32 + mi * 16 + (lane >> 2);
                    const int c0 = nw * 16 + ni * 8 + (lane & 3) * 2;
                    float* cx = &sm[SM_CEX + (kq * 64 + r) * 33 + c0];
                    cx[0]          = acc2[mi][ni][0];
                    cx[1]          = acc2[mi][ni][1];
                    cx[8 * 33]     = acc2[mi][ni][2];
                    cx[8 * 33 + 1] = acc2[mi][ni][3];
                }
            __syncthreads();
            float pre[4];
#pragma unroll
            for (int g = 0; g < 4; ++g) {
                float s = sm[SM_B2 + g * 8 + ej];
#pragma unroll
                for (int q = 0; q < 4; ++q)
                    s += sm[SM_CEX + (q * 64 + er) * 33 + g * 8 + ej];
                pre[g] = s;
            }
            const float ig = sigm(pre[0]), fg = sigm(pre[1]);
            const float gg = tanhf(pre[2]), og = sigm(pre[3]);
            const float cn = fg * c2s + ig * gg;
            c2s = cn;
            const float hv = og * tanhf(cn);
            g_h2f[(it + 1) & 1][mcta][hchunk][hidx] = to_tf32(hv);
            if (it == kT) g_h2p[(row0 + er) * kH + hbase + ej] = hv;
        }

        // ---- 2-level grid barrier ----
        __threadfence();
        __syncthreads();
        if (tid == 0) {
            unsigned a;
            asm volatile("atom.acq_rel.gpu.add.u32 %0, [%1], %2;"
                         : "=r"(a) : "l"(&g_leaf[grp * 32]), "r"(1u) : "memory");
            if (a == gen * 16 + 15) {
                unsigned r;
                asm volatile("atom.acq_rel.gpu.add.u32 %0, [%1], %2;"
                             : "=r"(r) : "l"(&g_root[0]), "r"(1u) : "memory");
                if (r == gen * 8 + 7) {
                    asm volatile("st.release.gpu.u32 [%0], %1;"
                                 :: "l"(&g_root[32]), "r"(gen + 1) : "memory");
                }
            }
            unsigned v;
            do {
                asm volatile("ld.acquire.gpu.u32 %0, [%1];"
                             : "=r"(v) : "l"(&g_root[32]) : "memory");
                if (v > gen) break;
                __nanosleep(64);
            } while (true);
        }
        ++gen;
        __syncthreads();
    }
}

// =====================================================================
// MODE 0: layer-0 input projection (out transposed to [t][b][4H]); MODE 1: FC.
// =====================================================================
template <int MODE, int KTOT>
__global__ __launch_bounds__(256) void k_io(
    const float* __restrict__ A0, const float* __restrict__ W0,
    const float* __restrict__ bias0, const float* __restrict__ bias1,
    float* __restrict__ outp)
{
    __shared__ float Asf[512];
    __shared__ float Bsf[2048];

    const int tid  = threadIdx.x;
    const int lane = tid & 31;
    const int w    = tid >> 5;
    const int mw   = w >> 2;
    const int nw   = w & 3;
    const int mtile = blockIdx.y;
    const int ntile = blockIdx.x;

    float acc[4][4];
#pragma unroll
    for (int j = 0; j < 4; j++)
#pragma unroll
        for (int q = 0; q < 4; q++) acc[j][q] = 0.0f;

    const int a_r  = tid >> 3;
    const int a_kk = (tid & 7) * 2;
    const int b_n   = tid >> 1;
    const int b_kk8 = (tid & 1) * 8;
    const int b_wrow = (MODE == 0) ? (ntile * 128 + b_n) : b_n;
    const int kw = (MODE == 0) ? kI : kH;

#pragma unroll 1
    for (int kt = 0; kt < KTOT; kt += 16) {
        {
            const int gm = mtile * 32 + a_r;
            const float2 v = *(const float2*)&A0[(size_t)gm * kw + kt + a_kk];
            const float vv[2] = { v.x, v.y };
#pragma unroll
            for (int e = 0; e < 2; ++e) {
                const int k = a_kk + e;
                const int g = (k >> 3) * 2 + (a_r >> 4);
                const int ln = ((a_r & 7) << 2) | (k & 3);
                const int comp = ((a_r >> 3) & 1) | (((k >> 2) & 1) << 1);
                Asf[(g * 32 + ln) * 4 + comp] = to_tf32(vv[e]);
            }
        }
        {
            const float4* p = (const float4*)&W0[(size_t)b_wrow * kw + kt + b_kk8];
            const float4 v0 = p[0], v1 = p[1];
            const float vv[8] = { v0.x, v0.y, v0.z, v0.w, v1.x, v1.y, v1.z, v1.w };
#pragma unroll
            for (int e = 0; e < 8; ++e) {
                const int k = b_kk8 + e;
                const int g = (k >> 3) * 16 + (b_n >> 3);
                const int ln = ((b_n & 7) << 2) | (k & 3);
                const int comp = (k >> 2) & 1;
                Bsf[(g * 32 + ln) * 2 + comp] = to_tf32(vv[e]);
            }
        }
        __syncthreads();

#pragma unroll
        for (int k8 = 0; k8 < 2; ++k8) {
            const float4 af = *(const float4*)&Asf[((k8 * 2 + mw) * 32 + lane) * 4];
            uint32_t au[4] = { __float_as_uint(af.x), __float_as_uint(af.y),
                               __float_as_uint(af.z), __float_as_uint(af.w) };
#pragma unroll
            for (int j = 0; j < 4; ++j) {
                const float2 b = *(const float2*)&Bsf[((k8 * 16 + nw * 4 + j) * 32 + lane) * 2];
                uint32_t bu[2] = { __float_as_uint(b.x), __float_as_uint(b.y) };
                mma_tf32(acc[j], au, bu);
            }
        }
        __syncthreads();
    }

    const int gr = mtile * 32 + mw * 16 + (lane >> 2);
    const int cbase = (MODE == 0 ? ntile * 128 : 0) + nw * 32 + (lane & 3) * 2;
    const size_t or0 = (MODE == 0)
        ? ((size_t)((gr & 255) * kB + (gr >> 8))) * kFH
        : (size_t)gr * kO;
    const size_t or1 = (MODE == 0)
        ? ((size_t)(((gr + 8) & 255) * kB + ((gr + 8) >> 8))) * kFH
        : (size_t)(gr + 8) * kO;
#pragma unroll
    for (int j = 0; j < 4; j++) {
        const int c0 = cbase + j * 8;
        float bv0, bv1;
        if (MODE == 0) {
            bv0 = bias0[c0] + bias1[c0];
            bv1 = bias0[c0 + 1] + bias1[c0 + 1];
        } else {
            bv0 = bias0[c0];
            bv1 = bias0[c0 + 1];
        }
        outp[or0 + c0]     = acc[j][0] + bv0;
        outp[or0 + c0 + 1] = acc[j][1] + bv1;
        outp[or1 + c0]     = acc[j][2] + bv0;
        outp[or1 + c0 + 1] = acc[j][3] + bv1;
    }
}

extern "C" void kernel_launch(void* const* d_in, const int* in_sizes, int n_in,
                              void* d_out, int out_size)
{
    const float* x     = (const float*)d_in[0];
    const float* W_ih0 = (const float*)d_in[1];
    const float* W_hh0 = (const float*)d_in[2];
    const float* b_ih0 = (const float*)d_in[3];
    const float* b_hh0 = (const float*)d_in[4];
    const float* W_ih1 = (const float*)d_in[5];
    const float* W_hh1 = (const float*)d_in[6];
    const float* b_ih1 = (const float*)d_in[7];
    const float* b_hh1 = (const float*)d_in[8];
    const float* fc_w  = (const float*)d_in[9];
    const float* fc_b  = (const float*)d_in[10];

    float *xp0p, *h1fp, *h2fp, *h2pp;
    unsigned *leafp, *rootp;
    cudaGetSymbolAddress((void**)&xp0p, g_xp0);
    cudaGetSymbolAddress((void**)&h1fp, g_h1f);
    cudaGetSymbolAddress((void**)&h2fp, g_h2f);
    cudaGetSymbolAddress((void**)&h2pp, g_h2p);
    cudaGetSymbolAddress((void**)&leafp, g_leaf);
    cudaGetSymbolAddress((void**)&rootp, g_root);

    static bool attr_set = false;
    if (!attr_set) {
        cudaFuncSetAttribute(k_scan, cudaFuncAttributeMaxDynamicSharedMemorySize,
                             (int)SMEM_BYTES);
        attr_set = true;
    }

    // Deterministic per-call init
    cudaMemsetAsync(h1fp, 0, sizeof(g_h1f), 0);
    cudaMemsetAsync(h2fp, 0, sizeof(g_h2f), 0);
    cudaMemsetAsync(leafp, 0, sizeof(g_leaf), 0);
    cudaMemsetAsync(rootp, 0, sizeof(g_root), 0);

    // Layer-0 input projection -> g_xp0 [t][b][4H]
    k_io<0, kI><<<dim3(16, kBT / 32), 256>>>(x, W_ih0, b_ih0, b_hh0, xp0p);

    // Persistent fused 2-layer scan
    k_scan<<<GRID, NTHR, SMEM_BYTES>>>(W_hh0, W_ih1, W_hh1, b_ih1, b_hh1);

    // FC head on final h2 (plain layout)
    k_io<1, kH><<<dim3(1, 4), 256>>>(h2pp, fc_w, fc_b, nullptr, (float*)d_out);
}

// round 7
// speedup vs baseline: 1.1785x; 1.1785x over previous
#include <cuda_runtime.h>
#include <cstdint>
#include <cstddef>

constexpr int kB = 128, kT = 256, kI = 256, kH = 512, kO = 128;
constexpr int kFH = 4 * kH, kBH = kB * kH, kBT = kB * kT;

// Scratch
__device__ float g_xp0[(size_t)kBT * kFH];     // [t][b][4H] layer-0 input proj
// h in mma-fragment-interleaved layout:
// [buf][mcta half][chunk of 64 k][4096]; element (r,k) of chunk ->
// (((k>>3)*4 + (r>>4))*32 + (((r&7)<<2)|(k&3)))*4 + ((r>>3)&1) + ((k>>2)&1)*2
__device__ float g_h1f[2][2][8][4096];
__device__ float g_h2f[2][2][8][4096];
__device__ float g_h2p[kBH];                   // plain final h2 for FC
__device__ unsigned g_leaf[8 * 32];            // leaf counters, 128B apart
__device__ unsigned g_root[64];                // [0]=count, [32]=generation

constexpr int GRID = 128, NTHR = 512;

// SMEM (floats)
constexpr int CEX_LD = 34;                     // EVEN stride: float2 stores stay 8B-aligned
constexpr int SM_WH0 = 0;                      // each W: 64 k8 x 4 tiles x 32 lanes x 2
constexpr int SM_WI1 = 16384;
constexpr int SM_WH1 = 32768;
constexpr int SM_CEX = 49152;                  // [4][64][CEX_LD] = 8704
constexpr int SM_B2  = SM_CEX + 4 * 64 * CEX_LD;   // 57856: layer-2 bias sums (32)
constexpr int SM_TOTF = SM_B2 + 32;            // 57888 floats = 231552 B
constexpr size_t SMEM_BYTES = (size_t)SM_TOTF * sizeof(float);

__device__ __forceinline__ float to_tf32(float x) {
    uint32_t u;
    asm("cvt.rna.tf32.f32 %0, %1;" : "=r"(u) : "f"(x));
    return __uint_as_float(u);
}

__device__ __forceinline__ void mma_tf32(float* d, const uint32_t* a, const uint32_t* b) {
    asm volatile(
        "mma.sync.aligned.m16n8k8.row.col.f32.tf32.tf32.f32 "
        "{%0,%1,%2,%3}, {%4,%5,%6,%7}, {%8,%9}, {%0,%1,%2,%3};\n"
        : "+f"(d[0]), "+f"(d[1]), "+f"(d[2]), "+f"(d[3])
        : "r"(a[0]), "r"(a[1]), "r"(a[2]), "r"(a[3]), "r"(b[0]), "r"(b[1]));
}

__device__ __forceinline__ float sigm(float x) { return 1.0f / (1.0f + expf(-x)); }

// =====================================================================
// Persistent fused 2-layer LSTM scan.
// CTA c: mcta=c&1 -> rows [mcta*64,+64); ncta=c>>1 -> h-cols [ncta*8,+8) of
// both layers (32 gate-cols). Iter it: layer-1 step it + layer-2 step it-1.
// 16 warps: kq=w&3 (k-split 4), mw=w>>2 (m16 stripe). Warp tile m16 x n32.
// Warp kq exclusively owns h1 chunks {2kq,2kq+1} (feeding acc1 AND acc2's
// h1-part) and h2 chunks {2kq,2kq+1} (acc2). A-frags direct LDG.128 (__ldcg)
// from frag-interleaved global h; NO mainloop synchronization.
// =====================================================================
__global__ void __launch_bounds__(NTHR, 1) k_scan(
    const float* __restrict__ Whh0, const float* __restrict__ Wih1,
    const float* __restrict__ Whh1, const float* __restrict__ bih1,
    const float* __restrict__ bhh1)
{
    extern __shared__ float sm[];
    const int tid  = threadIdx.x;
    const int lane = tid & 31;
    const int w    = tid >> 5;
    const int kq   = w & 3;
    const int mw   = w >> 2;     // 0..3 (m16 stripe)
    const int mcta = blockIdx.x & 1;
    const int ncta = blockIdx.x >> 1;
    const int hbase = ncta * 8;
    const int row0  = mcta * 64;
    const int grp   = blockIdx.x >> 4;

    // ---- Weight slices into SMEM, fragment-interleaved ----
    for (int i = tid; i < 32 * 512; i += NTHR) {
        const int cc = i >> 9, k = i & 511;
        const int grow = (cc >> 3) * kH + hbase + (cc & 7);
        const int idx = (((k >> 3) * 4 + (cc >> 3)) * 32 + (((cc & 7) << 2) | (k & 3))) * 2
                        + ((k >> 2) & 1);
        sm[SM_WH0 + idx] = to_tf32(Whh0[grow * kH + k]);
        sm[SM_WI1 + idx] = to_tf32(Wih1[grow * kH + k]);
        sm[SM_WH1 + idx] = to_tf32(Whh1[grow * kH + k]);
    }
    if (tid < 32) {
        const int grow = (tid >> 3) * kH + hbase + (tid & 7);
        sm[SM_B2 + tid] = bih1[grow] + bhh1[grow];
    }
    __syncthreads();

    const int er = tid >> 3;     // epilogue row (0..63)
    const int ej = tid & 7;      // epilogue h-col (0..7)
    const int hidx = ((((ncta & 7) * 4 + (er >> 4)) * 32 +
                      (((er & 7) << 2) | (ej & 3))) * 4) +
                     ((er >> 3) & 1) + (((ej >> 2) & 1) << 1);
    const int hchunk = ncta >> 3;
    const int foff = (mw * 32 + lane) * 4;   // a-frag base offset within (chunk,k8)

    float c1s = 0.f, c2s = 0.f;
    unsigned gen = 0;

    for (int it = 0; it <= kT; ++it) {
        const bool do1 = (it < kT);
        const bool do2 = (it >= 1);
        const float* __restrict__ h1r = &g_h1f[it & 1][mcta][0][0];
        const float* __restrict__ h2r = &g_h2f[it & 1][mcta][0][0];

        // Per-warp chunk bases: fi = cidx*8 + k8; cidx 0,1 -> h1, 2,3 -> h2
        const float* cbase[4];
        cbase[0] = h1r + (kq * 2 + 0) * 4096 + foff;
        cbase[1] = h1r + (kq * 2 + 1) * 4096 + foff;
        cbase[2] = h2r + (kq * 2 + 0) * 4096 + foff;
        cbase[3] = h2r + (kq * 2 + 1) * 4096 + foff;

        float acc1[4][4], acc2[4][4];
#pragma unroll
        for (int t = 0; t < 4; ++t)
#pragma unroll
            for (int q = 0; q < 4; ++q) { acc1[t][q] = 0.f; acc2[t][q] = 0.f; }

        // xp0 prefetch for layer-1 epilogue
        float px[4];
        if (do1) {
            const float* xpp = &g_xp0[((size_t)it * kB + row0 + er) * kFH + hbase + ej];
            px[0] = __ldg(xpp);
            px[1] = __ldg(xpp + kH);
            px[2] = __ldg(xpp + 2 * kH);
            px[3] = __ldg(xpp + 3 * kH);
        }

        // ---- mainloop: 32 a-frags via LDG.128 ring (depth 8), no syncs ----
        float4 ring[8];
#pragma unroll
        for (int i = 0; i < 8; ++i)
            ring[i] = __ldcg((const float4*)(cbase[i >> 3] + (i & 7) * 512));

#pragma unroll 8
        for (int fi = 0; fi < 32; ++fi) {
            const float4 af = ring[fi & 7];
            if (fi + 8 < 32)
                ring[fi & 7] = __ldcg((const float4*)(cbase[(fi + 8) >> 3]
                                                      + ((fi + 8) & 7) * 512));
            uint32_t au[4] = { __float_as_uint(af.x), __float_as_uint(af.y),
                               __float_as_uint(af.z), __float_as_uint(af.w) };
            const int cidx = fi >> 3;
            const int k8   = fi & 7;
            if (cidx < 2) {
                const int k8g = (kq * 2 + cidx) * 8 + k8;
#pragma unroll
                for (int t = 0; t < 4; ++t) {
                    const float2 b1 = *(const float2*)&sm[SM_WH0 +
                        ((k8g * 4 + t) * 32 + lane) * 2];
                    uint32_t bu1[2] = { __float_as_uint(b1.x), __float_as_uint(b1.y) };
                    mma_tf32(acc1[t], au, bu1);
                    const float2 b2 = *(const float2*)&sm[SM_WI1 +
                        ((k8g * 4 + t) * 32 + lane) * 2];
                    uint32_t bu2[2] = { __float_as_uint(b2.x), __float_as_uint(b2.y) };
                    mma_tf32(acc2[t], au, bu2);
                }
            } else {
                const int k8g = (kq * 2 + (cidx - 2)) * 8 + k8;
#pragma unroll
                for (int t = 0; t < 4; ++t) {
                    const float2 b = *(const float2*)&sm[SM_WH1 +
                        ((k8g * 4 + t) * 32 + lane) * 2];
                    uint32_t bu[2] = { __float_as_uint(b.x), __float_as_uint(b.y) };
                    mma_tf32(acc2[t], au, bu);
                }
            }
        }

        // ---- Layer-1 epilogue: k-split-4 reduce + cell update ----
        if (do1) {
            const int r  = mw * 16 + (lane >> 2);
            const int cb = (lane & 3) * 2;
#pragma unroll
            for (int t = 0; t < 4; ++t) {
                float* cx = &sm[SM_CEX + (kq * 64 + r) * CEX_LD + t * 8 + cb];
                *(float2*)cx                  = make_float2(acc1[t][0], acc1[t][1]);
                *(float2*)(cx + 8 * CEX_LD)   = make_float2(acc1[t][2], acc1[t][3]);
            }
            __syncthreads();
            float pre[4];
#pragma unroll
            for (int g = 0; g < 4; ++g) {
                float s = px[g];
#pragma unroll
                for (int q = 0; q < 4; ++q)
                    s += sm[SM_CEX + (q * 64 + er) * CEX_LD + g * 8 + ej];
                pre[g] = s;
            }
            const float ig = sigm(pre[0]), fg = sigm(pre[1]);
            const float gg = tanhf(pre[2]), og = sigm(pre[3]);
            const float cn = fg * c1s + ig * gg;
            c1s = cn;
            g_h1f[(it + 1) & 1][mcta][hchunk][hidx] = to_tf32(og * tanhf(cn));
            __syncthreads();
        }

        // ---- Layer-2 epilogue ----
        if (do2) {
            const int r  = mw * 16 + (lane >> 2);
            const int cb = (lane & 3) * 2;
#pragma unroll
            for (int t = 0; t < 4; ++t) {
                float* cx = &sm[SM_CEX + (kq * 64 + r) * CEX_LD + t * 8 + cb];
                *(float2*)cx                  = make_float2(acc2[t][0], acc2[t][1]);
                *(float2*)(cx + 8 * CEX_LD)   = make_float2(acc2[t][2], acc2[t][3]);
            }
            __syncthreads();
            float pre[4];
#pragma unroll
            for (int g = 0; g < 4; ++g) {
                float s = sm[SM_B2 + g * 8 + ej];
#pragma unroll
                for (int q = 0; q < 4; ++q)
                    s += sm[SM_CEX + (q * 64 + er) * CEX_LD + g * 8 + ej];
                pre[g] = s;
            }
            const float ig = sigm(pre[0]), fg = sigm(pre[1]);
            const float gg = tanhf(pre[2]), og = sigm(pre[3]);
            const float cn = fg * c2s + ig * gg;
            c2s = cn;
            const float hv = og * tanhf(cn);
            g_h2f[(it + 1) & 1][mcta][hchunk][hidx] = to_tf32(hv);
            if (it == kT) g_h2p[(row0 + er) * kH + hbase + ej] = hv;
        }

        // ---- 2-level grid barrier ----
        __threadfence();
        __syncthreads();
        if (tid == 0) {
            unsigned a;
            asm volatile("atom.acq_rel.gpu.add.u32 %0, [%1], %2;"
                         : "=r"(a) : "l"(&g_leaf[grp * 32]), "r"(1u) : "memory");
            if (a == gen * 16 + 15) {
                unsigned r;
                asm volatile("atom.acq_rel.gpu.add.u32 %0, [%1], %2;"
                             : "=r"(r) : "l"(&g_root[0]), "r"(1u) : "memory");
                if (r == gen * 8 + 7) {
                    asm volatile("st.release.gpu.u32 [%0], %1;"
                                 :: "l"(&g_root[32]), "r"(gen + 1) : "memory");
                }
            }
            unsigned v;
            do {
                asm volatile("ld.acquire.gpu.u32 %0, [%1];"
                             : "=r"(v) : "l"(&g_root[32]) : "memory");
                if (v > gen) break;
                __nanosleep(64);
            } while (true);
        }
        ++gen;
        __syncthreads();
    }
}

// =====================================================================
// MODE 0: layer-0 input projection (out transposed to [t][b][4H]); MODE 1: FC.
// =====================================================================
template <int MODE, int KTOT>
__global__ __launch_bounds__(256) void k_io(
    const float* __restrict__ A0, const float* __restrict__ W0,
    const float* __restrict__ bias0, const float* __restrict__ bias1,
    float* __restrict__ outp)
{
    __shared__ float Asf[512];
    __shared__ float Bsf[2048];

    const int tid  = threadIdx.x;
    const int lane = tid & 31;
    const int w    = tid >> 5;
    const int mw   = w >> 2;
    const int nw   = w & 3;
    const int mtile = blockIdx.y;
    const int ntile = blockIdx.x;

    float acc[4][4];
#pragma unroll
    for (int j = 0; j < 4; j++)
#pragma unroll
        for (int q = 0; q < 4; q++) acc[j][q] = 0.0f;

    const int a_r  = tid >> 3;
    const int a_kk = (tid & 7) * 2;
    const int b_n   = tid >> 1;
    const int b_kk8 = (tid & 1) * 8;
    const int b_wrow = (MODE == 0) ? (ntile * 128 + b_n) : b_n;
    const int kw = (MODE == 0) ? kI : kH;

#pragma unroll 1
    for (int kt = 0; kt < KTOT; kt += 16) {
        {
            const int gm = mtile * 32 + a_r;
            const float2 v = *(const float2*)&A0[(size_t)gm * kw + kt + a_kk];
            const float vv[2] = { v.x, v.y };
#pragma unroll
            for (int e = 0; e < 2; ++e) {
                const int k = a_kk + e;
                const int g = (k >> 3) * 2 + (a_r >> 4);
                const int ln = ((a_r & 7) << 2) | (k & 3);
                const int comp = ((a_r >> 3) & 1) | (((k >> 2) & 1) << 1);
                Asf[(g * 32 + ln) * 4 + comp] = to_tf32(vv[e]);
            }
        }
        {
            const float4* p = (const float4*)&W0[(size_t)b_wrow * kw + kt + b_kk8];
            const float4 v0 = p[0], v1 = p[1];
            const float vv[8] = { v0.x, v0.y, v0.z, v0.w, v1.x, v1.y, v1.z, v1.w };
#pragma unroll
            for (int e = 0; e < 8; ++e) {
                const int k = b_kk8 + e;
                const int g = (k >> 3) * 16 + (b_n >> 3);
                const int ln = ((b_n & 7) << 2) | (k & 3);
                const int comp = (k >> 2) & 1;
                Bsf[(g * 32 + ln) * 2 + comp] = to_tf32(vv[e]);
            }
        }
        __syncthreads();

#pragma unroll
        for (int k8 = 0; k8 < 2; ++k8) {
            const float4 af = *(const float4*)&Asf[((k8 * 2 + mw) * 32 + lane) * 4];
            uint32_t au[4] = { __float_as_uint(af.x), __float_as_uint(af.y),
                               __float_as_uint(af.z), __float_as_uint(af.w) };
#pragma unroll
            for (int j = 0; j < 4; ++j) {
                const float2 b = *(const float2*)&Bsf[((k8 * 16 + nw * 4 + j) * 32 + lane) * 2];
                uint32_t bu[2] = { __float_as_uint(b.x), __float_as_uint(b.y) };
                mma_tf32(acc[j], au, bu);
            }
        }
        __syncthreads();
    }

    const int gr = mtile * 32 + mw * 16 + (lane >> 2);
    const int cbase = (MODE == 0 ? ntile * 128 : 0) + nw * 32 + (lane & 3) * 2;
    const size_t or0 = (MODE == 0)
        ? ((size_t)((gr & 255) * kB + (gr >> 8))) * kFH
        : (size_t)gr * kO;
    const size_t or1 = (MODE == 0)
        ? ((size_t)(((gr + 8) & 255) * kB + ((gr + 8) >> 8))) * kFH
        : (size_t)(gr + 8) * kO;
#pragma unroll
    for (int j = 0; j < 4; j++) {
        const int c0 = cbase + j * 8;
        float bv0, bv1;
        if (MODE == 0) {
            bv0 = bias0[c0] + bias1[c0];
            bv1 = bias0[c0 + 1] + bias1[c0 + 1];
        } else {
            bv0 = bias0[c0];
            bv1 = bias0[c0 + 1];
        }
        outp[or0 + c0]     = acc[j][0] + bv0;
        outp[or0 + c0 + 1] = acc[j][1] + bv1;
        outp[or1 + c0]     = acc[j][2] + bv0;
        outp[or1 + c0 + 1] = acc[j][3] + bv1;
    }
}

extern "C" void kernel_launch(void* const* d_in, const int* in_sizes, int n_in,
                              void* d_out, int out_size)
{
    const float* x     = (const float*)d_in[0];
    const float* W_ih0 = (const float*)d_in[1];
    const float* W_hh0 = (const float*)d_in[2];
    const float* b_ih0 = (const float*)d_in[3];
    const float* b_hh0 = (const float*)d_in[4];
    const float* W_ih1 = (const float*)d_in[5];
    const float* W_hh1 = (const float*)d_in[6];
    const float* b_ih1 = (const float*)d_in[7];
    const float* b_hh1 = (const float*)d_in[8];
    const float* fc_w  = (const float*)d_in[9];
    const float* fc_b  = (const float*)d_in[10];

    float *xp0p, *h1fp, *h2fp, *h2pp;
    unsigned *leafp, *rootp;
    cudaGetSymbolAddress((void**)&xp0p, g_xp0);
    cudaGetSymbolAddress((void**)&h1fp, g_h1f);
    cudaGetSymbolAddress((void**)&h2fp, g_h2f);
    cudaGetSymbolAddress((void**)&h2pp, g_h2p);
    cudaGetSymbolAddress((void**)&leafp, g_leaf);
    cudaGetSymbolAddress((void**)&rootp, g_root);

    static bool attr_set = false;
    if (!attr_set) {
        cudaFuncSetAttribute(k_scan, cudaFuncAttributeMaxDynamicSharedMemorySize,
                             (int)SMEM_BYTES);
        attr_set = true;
    }

    // Deterministic per-call init
    cudaMemsetAsync(h1fp, 0, sizeof(g_h1f), 0);
    cudaMemsetAsync(h2fp, 0, sizeof(g_h2f), 0);
    cudaMemsetAsync(leafp, 0, sizeof(g_leaf), 0);
    cudaMemsetAsync(rootp, 0, sizeof(g_root), 0);

    // Layer-0 input projection -> g_xp0 [t][b][4H]
    k_io<0, kI><<<dim3(16, kBT / 32), 256>>>(x, W_ih0, b_ih0, b_hh0, xp0p);

    // Persistent fused 2-layer scan
    k_scan<<<GRID, NTHR, SMEM_BYTES>>>(W_hh0, W_ih1, W_hh1, b_ih1, b_hh1);

    // FC head on final h2 (plain layout)
    k_io<1, kH><<<dim3(1, 4), 256>>>(h2pp, fc_w, fc_b, nullptr, (float*)d_out);
}

// round 9
// speedup vs baseline: 1.4312x; 1.2145x over previous
#include <cuda_runtime.h>
#include <cstdint>
#include <cstddef>

constexpr int kB = 128, kT = 256, kI = 256, kH = 512, kO = 128;
constexpr int kFH = 4 * kH, kBH = kB * kH;

// Scratch
// x transposed to mma-fragment-interleaved: [t][mcta][kchunk of 64][4096]
__device__ float g_xf[kT][2][4][4096];
// W_ih0 per-ncta slice, frag-interleaved: [ncta][32 k8 x 4 t x 32 lanes x 2]
__device__ float g_wf[64][8192];
// h in frag-interleaved layout: [buf][mcta][chunk of 64 k][4096]
__device__ float g_h1f[2][2][8][4096];
__device__ float g_h2f[2][2][8][4096];
__device__ float g_h2p[kBH];                   // plain final h2 for FC
__device__ unsigned g_leaf[8 * 32];
__device__ unsigned g_root[64];                // [0]=count, [32]=generation

constexpr int GRID = 128, NTHR = 512;

// SMEM (floats)
constexpr int CEX_LD = 34;
constexpr int SM_WH0 = 0;
constexpr int SM_WI1 = 16384;
constexpr int SM_WH1 = 32768;
constexpr int SM_CEX = 49152;                       // [4][64][34] = 8704
constexpr int SM_B1  = SM_CEX + 4 * 64 * CEX_LD;    // 57856: l1 bias sums (32)
constexpr int SM_B2  = SM_B1 + 32;                  // 57888: l2 bias sums (32)
constexpr int SM_TOTF = SM_B2 + 32;                 // 57920 fl = 231680 B
constexpr size_t SMEM_BYTES = (size_t)SM_TOTF * sizeof(float);

__device__ __forceinline__ float to_tf32(float x) {
    uint32_t u;
    asm("cvt.rna.tf32.f32 %0, %1;" : "=r"(u) : "f"(x));
    return __uint_as_float(u);
}

__device__ __forceinline__ void mma_tf32(float* d, const uint32_t* a, const uint32_t* b) {
    asm volatile(
        "mma.sync.aligned.m16n8k8.row.col.f32.tf32.tf32.f32 "
        "{%0,%1,%2,%3}, {%4,%5,%6,%7}, {%8,%9}, {%0,%1,%2,%3};\n"
        : "+f"(d[0]), "+f"(d[1]), "+f"(d[2]), "+f"(d[3])
        : "r"(a[0]), "r"(a[1]), "r"(a[2]), "r"(a[3]), "r"(b[0]), "r"(b[1]));
}

__device__ __forceinline__ float sigm(float x) { return 1.0f / (1.0f + expf(-x)); }

// =====================================================================
// One-time transpose: x -> g_xf (frag-interleaved), W_ih0 -> g_wf slices.
// =====================================================================
__global__ void __launch_bounds__(256) k_prep(const float* __restrict__ x,
                                              const float* __restrict__ Wih0)
{
    __shared__ float tile[64][68];   // 272B rows: EVERY row 16B-aligned for STS.128
    const int tid = threadIdx.x;
    const int u = blockIdx.x;
    if (u < 2048) {
        const int ch = u & 3, mc = (u >> 2) & 1, t = u >> 3;
#pragma unroll
        for (int p = 0; p < 4; ++p) {
            const int v = tid + p * 256;
            const int r = v >> 4, k4 = v & 15;
            const float4 val = __ldg((const float4*)&x[
                (size_t)(mc * 64 + r) * (kT * kI) + (size_t)t * kI + ch * 64 + k4 * 4]);
            *(float4*)&tile[r][k4 * 4] = val;
        }
        __syncthreads();
        float* dst = &g_xf[t][mc][ch][0];
#pragma unroll
        for (int p = 0; p < 4; ++p) {
            const int base = (tid + p * 256) * 4;
            float ov[4];
#pragma unroll
            for (int e = 0; e < 4; ++e) {
                const int idx = base + e;
                const int k8 = idx >> 9, rt = (idx >> 7) & 3;
                const int ln = (idx >> 2) & 31, comp = idx & 3;
                const int r = rt * 16 + ((comp & 1) << 3) + (ln >> 2);
                const int k = k8 * 8 + ((comp >> 1) << 2) + (ln & 3);
                ov[e] = to_tf32(tile[r][k]);
            }
            *(float4*)&dst[base] = make_float4(ov[0], ov[1], ov[2], ov[3]);
        }
    } else {
        const int nc = u - 2048;
        float* dst = &g_wf[nc][0];
#pragma unroll
        for (int p = 0; p < 8; ++p) {
            const int base = (tid + p * 256) * 4;
            float ov[4];
#pragma unroll
            for (int e = 0; e < 4; ++e) {
                const int idx = base + e;
                const int k8 = idx >> 8, g = (idx >> 6) & 3;
                const int ln = (idx >> 1) & 31, c2 = idx & 1;
                const int k = k8 * 8 + (c2 << 2) + (ln & 3);
                const int grow = g * kH + nc * 8 + (ln >> 2);
                ov[e] = to_tf32(Wih0[grow * kI + k]);
            }
            *(float4*)&dst[base] = make_float4(ov[0], ov[1], ov[2], ov[3]);
        }
    }
}

// =====================================================================
// Persistent fused 2-layer LSTM scan with x-GEMM fused (no xp0 buffer).
// CTA c: mcta=c&1 rows [mcta*64,+64); ncta=c>>1 h-cols [ncta*8,+8).
// 16 warps: kq=w&3 (k-split 4), mw=w>>2 (m16 stripe), warp tile m16 x n32.
// Sections per iter: X (x@Wih0 -> acc1, K=256 split 4 ways = 8 k8/warp),
// H1A/H1B (h1@Whh0 -> acc1, h1@Wih1 -> acc2), H2A/H2B (h2@Whh1 -> acc2).
// A-frags via LDG.128 ring; Wih0 b-frags via 3-deep register prefetch from
// L2; next-iter x/W loads hoisted BEFORE the grid barrier.
// =====================================================================
__global__ void __launch_bounds__(NTHR, 1) k_scan(
    const float* __restrict__ Whh0, const float* __restrict__ Wih1,
    const float* __restrict__ Whh1,
    const float* __restrict__ bih0, const float* __restrict__ bhh0,
    const float* __restrict__ bih1, const float* __restrict__ bhh1)
{
    extern __shared__ float sm[];
    const int tid  = threadIdx.x;
    const int lane = tid & 31;
    const int w    = tid >> 5;
    const int kq   = w & 3;
    const int mw   = w >> 2;
    const int mcta = blockIdx.x & 1;
    const int ncta = blockIdx.x >> 1;
    const int hbase = ncta * 8;
    const int row0  = mcta * 64;
    const int grp   = blockIdx.x >> 4;

    // ---- Weight slices into SMEM, fragment-interleaved ----
    for (int i = tid; i < 32 * 512; i += NTHR) {
        const int cc = i >> 9, k = i & 511;
        const int grow = (cc >> 3) * kH + hbase + (cc & 7);
        const int idx = (((k >> 3) * 4 + (cc >> 3)) * 32 + (((cc & 7) << 2) | (k & 3))) * 2
                        + ((k >> 2) & 1);
        sm[SM_WH0 + idx] = to_tf32(Whh0[grow * kH + k]);
        sm[SM_WI1 + idx] = to_tf32(Wih1[grow * kH + k]);
        sm[SM_WH1 + idx] = to_tf32(Whh1[grow * kH + k]);
    }
    if (tid < 32) {
        const int grow = (tid >> 3) * kH + hbase + (tid & 7);
        sm[SM_B1 + tid] = bih0[grow] + bhh0[grow];
        sm[SM_B2 + tid] = bih1[grow] + bhh1[grow];
    }
    __syncthreads();

    const int er = tid >> 3;
    const int ej = tid & 7;
    const int hidx = ((((ncta & 7) * 4 + (er >> 4)) * 32 +
                      (((er & 7) << 2) | (ej & 3))) * 4) +
                     ((er >> 3) & 1) + (((ej >> 2) & 1) << 1);
    const int hchunk = ncta >> 3;
    const int foff = (mw * 32 + lane) * 4;
    const float* __restrict__ wfp = &g_wf[ncta][0];

    float c1s = 0.f, c2s = 0.f;
    unsigned gen = 0;

    float4 ring[8];
    float2 wv[3][4];

    // Issue x-frags + W-frags for iteration `itx` (static data, barrier-free)
    auto issue_x = [&](int itx) {
        const float* cbx = &g_xf[itx][mcta][kq][0] + foff;
#pragma unroll
        for (int j = 0; j < 8; ++j)
            ring[j] = __ldcg((const float4*)(cbx + j * 512));
#pragma unroll
        for (int g = 0; g < 3; ++g)
#pragma unroll
            for (int t = 0; t < 4; ++t)
                wv[g][t] = __ldcg((const float2*)(wfp +
                    (((kq * 8 + g) * 4 + t) * 32 + lane) * 2));
    };

    issue_x(0);

    for (int it = 0; it <= kT; ++it) {
        const bool do1 = (it < kT);
        const bool do2 = (it >= 1);
        const float* __restrict__ h1r = &g_h1f[it & 1][mcta][0][0];
        const float* __restrict__ h2r = &g_h2f[it & 1][mcta][0][0];

        const float* cb1a = h1r + (kq * 2 + 0) * 4096 + foff;
        const float* cb1b = h1r + (kq * 2 + 1) * 4096 + foff;
        const float* cb2a = h2r + (kq * 2 + 0) * 4096 + foff;
        const float* cb2b = h2r + (kq * 2 + 1) * 4096 + foff;

        float acc1[4][4], acc2[4][4];
#pragma unroll
        for (int t = 0; t < 4; ++t)
#pragma unroll
            for (int q = 0; q < 4; ++q) { acc1[t][q] = 0.f; acc2[t][q] = 0.f; }

        if (!do1) {
            // no x section this iter: load h1 chunk A into ring post-barrier
#pragma unroll
            for (int j = 0; j < 8; ++j)
                ring[j] = __ldcg((const float4*)(cb1a + j * 512));
        }

        // ---- Section X: x @ Wih0 -> acc1; prefetch h1 chunk A ----
        if (do1) {
#pragma unroll
            for (int j = 0; j < 8; ++j) {
                const float4 af = ring[j];
                ring[j] = __ldcg((const float4*)(cb1a + j * 512));
                uint32_t au[4] = { __float_as_uint(af.x), __float_as_uint(af.y),
                                   __float_as_uint(af.z), __float_as_uint(af.w) };
#pragma unroll
                for (int t = 0; t < 4; ++t) {
                    float2 bb = wv[j % 3][t];
                    uint32_t bu[2] = { __float_as_uint(bb.x), __float_as_uint(bb.y) };
                    mma_tf32(acc1[t], au, bu);
                }
                if (j + 3 < 8) {
#pragma unroll
                    for (int t = 0; t < 4; ++t)
                        wv[j % 3][t] = __ldcg((const float2*)(wfp +
                            (((kq * 8 + j + 3) * 4 + t) * 32 + lane) * 2));
                }
            }
        }

        // ---- Section H1A: prefetch h1 chunk B ----
#pragma unroll
        for (int j = 0; j < 8; ++j) {
            const float4 af = ring[j];
            ring[j] = __ldcg((const float4*)(cb1b + j * 512));
            uint32_t au[4] = { __float_as_uint(af.x), __float_as_uint(af.y),
                               __float_as_uint(af.z), __float_as_uint(af.w) };
            const int k8g = (kq * 2) * 8 + j;
            if (do1) {
#pragma unroll
                for (int t = 0; t < 4; ++t) {
                    const float2 bb = *(const float2*)&sm[SM_WH0 +
                        ((k8g * 4 + t) * 32 + lane) * 2];
                    uint32_t bu[2] = { __float_as_uint(bb.x), __float_as_uint(bb.y) };
                    mma_tf32(acc1[t], au, bu);
                }
            }
            if (do2) {
#pragma unroll
                for (int t = 0; t < 4; ++t) {
                    const float2 bb = *(const float2*)&sm[SM_WI1 +
                        ((k8g * 4 + t) * 32 + lane) * 2];
                    uint32_t bu[2] = { __float_as_uint(bb.x), __float_as_uint(bb.y) };
                    mma_tf32(acc2[t], au, bu);
                }
            }
        }

        // ---- Section H1B: prefetch h2 chunk A (if needed) ----
#pragma unroll
        for (int j = 0; j < 8; ++j) {
            const float4 af = ring[j];
            if (do2) ring[j] = __ldcg((const float4*)(cb2a + j * 512));
            uint32_t au[4] = { __float_as_uint(af.x), __float_as_uint(af.y),
                               __float_as_uint(af.z), __float_as_uint(af.w) };
            const int k8g = (kq * 2 + 1) * 8 + j;
            if (do1) {
#pragma unroll
                for (int t = 0; t < 4; ++t) {
                    const float2 bb = *(const float2*)&sm[SM_WH0 +
                        ((k8g * 4 + t) * 32 + lane) * 2];
                    uint32_t bu[2] = { __float_as_uint(bb.x), __float_as_uint(bb.y) };
                    mma_tf32(acc1[t], au, bu);
                }
            }
            if (do2) {
#pragma unroll
                for (int t = 0; t < 4; ++t) {
                    const float2 bb = *(const float2*)&sm[SM_WI1 +
                        ((k8g * 4 + t) * 32 + lane) * 2];
                    uint32_t bu[2] = { __float_as_uint(bb.x), __float_as_uint(bb.y) };
                    mma_tf32(acc2[t], au, bu);
                }
            }
        }

        // ---- Sections H2A/H2B: h2 @ Whh1 -> acc2 ----
        if (do2) {
#pragma unroll
            for (int j = 0; j < 8; ++j) {
                const float4 af = ring[j];
                ring[j] = __ldcg((const float4*)(cb2b + j * 512));
                uint32_t au[4] = { __float_as_uint(af.x), __float_as_uint(af.y),
                                   __float_as_uint(af.z), __float_as_uint(af.w) };
                const int k8g = (kq * 2) * 8 + j;
#pragma unroll
                for (int t = 0; t < 4; ++t) {
                    const float2 bb = *(const float2*)&sm[SM_WH1 +
                        ((k8g * 4 + t) * 32 + lane) * 2];
                    uint32_t bu[2] = { __float_as_uint(bb.x), __float_as_uint(bb.y) };
                    mma_tf32(acc2[t], au, bu);
                }
            }
#pragma unroll
            for (int j = 0; j < 8; ++j) {
                const float4 af = ring[j];
                uint32_t au[4] = { __float_as_uint(af.x), __float_as_uint(af.y),
                                   __float_as_uint(af.z), __float_as_uint(af.w) };
                const int k8g = (kq * 2 + 1) * 8 + j;
#pragma unroll
                for (int t = 0; t < 4; ++t) {
                    const float2 bb = *(const float2*)&sm[SM_WH1 +
                        ((k8g * 4 + t) * 32 + lane) * 2];
                    uint32_t bu[2] = { __float_as_uint(bb.x), __float_as_uint(bb.y) };
                    mma_tf32(acc2[t], au, bu);
                }
            }
        }

        // Hoist next iteration's x/W loads (static data) ahead of epilogue+barrier
        if (it + 1 < kT) issue_x(it + 1);

        // ---- Layer-1 epilogue ----
        if (do1) {
            const int r  = mw * 16 + (lane >> 2);
            const int cb = (lane & 3) * 2;
#pragma unroll
            for (int t = 0; t < 4; ++t) {
                float* cx = &sm[SM_CEX + (kq * 64 + r) * CEX_LD + t * 8 + cb];
                *(float2*)cx                = make_float2(acc1[t][0], acc1[t][1]);
                *(float2*)(cx + 8 * CEX_LD) = make_float2(acc1[t][2], acc1[t][3]);
            }
            __syncthreads();
            float pre[4];
#pragma unroll
            for (int g = 0; g < 4; ++g) {
                float s = sm[SM_B1 + g * 8 + ej];
#pragma unroll
                for (int q = 0; q < 4; ++q)
                    s += sm[SM_CEX + (q * 64 + er) * CEX_LD + g * 8 + ej];
                pre[g] = s;
            }
            const float ig = sigm(pre[0]), fg = sigm(pre[1]);
            const float gg = tanhf(pre[2]), og = sigm(pre[3]);
            const float cn = fg * c1s + ig * gg;
            c1s = cn;
            g_h1f[(it + 1) & 1][mcta][hchunk][hidx] = to_tf32(og * tanhf(cn));
            __syncthreads();
        }

        // ---- Layer-2 epilogue ----
        if (do2) {
            const int r  = mw * 16 + (lane >> 2);
            const int cb = (lane & 3) * 2;
#pragma unroll
            for (int t = 0; t < 4; ++t) {
                float* cx = &sm[SM_CEX + (kq * 64 + r) * CEX_LD + t * 8 + cb];
                *(float2*)cx                = make_float2(acc2[t][0], acc2[t][1]);
                *(float2*)(cx + 8 * CEX_LD) = make_float2(acc2[t][2], acc2[t][3]);
            }
            __syncthreads();
            float pre[4];
#pragma unroll
            for (int g = 0; g < 4; ++g) {
                float s = sm[SM_B2 + g * 8 + ej];
#pragma unroll
                for (int q = 0; q < 4; ++q)
                    s += sm[SM_CEX + (q * 64 + er) * CEX_LD + g * 8 + ej];
                pre[g] = s;
            }
            const float ig = sigm(pre[0]), fg = sigm(pre[1]);
            const float gg = tanhf(pre[2]), og = sigm(pre[3]);
            const float cn = fg * c2s + ig * gg;
            c2s = cn;
            const float hv = og * tanhf(cn);
            g_h2f[(it + 1) & 1][mcta][hchunk][hidx] = to_tf32(hv);
            if (it == kT) g_h2p[(row0 + er) * kH + hbase + ej] = hv;
        }

        // ---- 2-level grid barrier ----
        __threadfence();
        __syncthreads();
        if (tid == 0) {
            unsigned a;
            asm volatile("atom.acq_rel.gpu.add.u32 %0, [%1], %2;"
                         : "=r"(a) : "l"(&g_leaf[grp * 32]), "r"(1u) : "memory");
            if (a == gen * 16 + 15) {
                unsigned r;
                asm volatile("atom.acq_rel.gpu.add.u32 %0, [%1], %2;"
                             : "=r"(r) : "l"(&g_root[0]), "r"(1u) : "memory");
                if (r == gen * 8 + 7) {
                    asm volatile("st.release.gpu.u32 [%0], %1;"
                                 :: "l"(&g_root[32]), "r"(gen + 1) : "memory");
                }
            }
            unsigned v;
            do {
                asm volatile("ld.acquire.gpu.u32 %0, [%1];"
                             : "=r"(v) : "l"(&g_root[32]) : "memory");
                if (v > gen) break;
                __nanosleep(64);
            } while (true);
        }
        ++gen;
        __syncthreads();
    }
}

// =====================================================================
// FC head: out = h2_final @ fc_w^T + fc_b
// =====================================================================
__global__ __launch_bounds__(256) void k_fc(
    const float* __restrict__ A0, const float* __restrict__ W0,
    const float* __restrict__ bias0, float* __restrict__ outp)
{
    __shared__ float Asf[512];
    __shared__ float Bsf[2048];

    const int tid  = threadIdx.x;
    const int lane = tid & 31;
    const int w    = tid >> 5;
    const int mw   = w >> 2;
    const int nw   = w & 3;
    const int mtile = blockIdx.y;

    float acc[4][4];
#pragma unroll
    for (int j = 0; j < 4; j++)
#pragma unroll
        for (int q = 0; q < 4; q++) acc[j][q] = 0.0f;

    const int a_r  = tid >> 3;
    const int a_kk = (tid & 7) * 2;
    const int b_n   = tid >> 1;
    const int b_kk8 = (tid & 1) * 8;

#pragma unroll 1
    for (int kt = 0; kt < kH; kt += 16) {
        {
            const int gm = mtile * 32 + a_r;
            const float2 v = *(const float2*)&A0[(size_t)gm * kH + kt + a_kk];
            const float vv[2] = { v.x, v.y };
#pragma unroll
            for (int e = 0; e < 2; ++e) {
                const int k = a_kk + e;
                const int g = (k >> 3) * 2 + (a_r >> 4);
                const int ln = ((a_r & 7) << 2) | (k & 3);
                const int comp = ((a_r >> 3) & 1) | (((k >> 2) & 1) << 1);
                Asf[(g * 32 + ln) * 4 + comp] = to_tf32(vv[e]);
            }
        }
        {
            const float4* p = (const float4*)&W0[(size_t)b_n * kH + kt + b_kk8];
            const float4 v0 = p[0], v1 = p[1];
            const float vv[8] = { v0.x, v0.y, v0.z, v0.w, v1.x, v1.y, v1.z, v1.w };
#pragma unroll
            for (int e = 0; e < 8; ++e) {
                const int k = b_kk8 + e;
                const int g = (k >> 3) * 16 + (b_n >> 3);
                const int ln = ((b_n & 7) << 2) | (k & 3);
                const int comp = (k >> 2) & 1;
                Bsf[(g * 32 + ln) * 2 + comp] = to_tf32(vv[e]);
            }
        }
        __syncthreads();

#pragma unroll
        for (int k8 = 0; k8 < 2; ++k8) {
            const float4 af = *(const float4*)&Asf[((k8 * 2 + mw) * 32 + lane) * 4];
            uint32_t au[4] = { __float_as_uint(af.x), __float_as_uint(af.y),
                               __float_as_uint(af.z), __float_as_uint(af.w) };
#pragma unroll
            for (int j = 0; j < 4; ++j) {
                const float2 b = *(const float2*)&Bsf[((k8 * 16 + nw * 4 + j) * 32 + lane) * 2];
                uint32_t bu[2] = { __float_as_uint(b.x), __float_as_uint(b.y) };
                mma_tf32(acc[j], au, bu);
            }
        }
        __syncthreads();
    }

    const int gr = mtile * 32 + mw * 16 + (lane >> 2);
    const int cbase = nw * 32 + (lane & 3) * 2;
#pragma unroll
    for (int j = 0; j < 4; j++) {
        const int c0 = cbase + j * 8;
        const float bv0 = bias0[c0];
        const float bv1 = bias0[c0 + 1];
        outp[(size_t)gr * kO + c0]           = acc[j][0] + bv0;
        outp[(size_t)gr * kO + c0 + 1]       = acc[j][1] + bv1;
        outp[(size_t)(gr + 8) * kO + c0]     = acc[j][2] + bv0;
        outp[(size_t)(gr + 8) * kO + c0 + 1] = acc[j][3] + bv1;
    }
}

extern "C" void kernel_launch(void* const* d_in, const int* in_sizes, int n_in,
                              void* d_out, int out_size)
{
    const float* x     = (const float*)d_in[0];
    const float* W_ih0 = (const float*)d_in[1];
    const float* W_hh0 = (const float*)d_in[2];
    const float* b_ih0 = (const float*)d_in[3];
    const float* b_hh0 = (const float*)d_in[4];
    const float* W_ih1 = (const float*)d_in[5];
    const float* W_hh1 = (const float*)d_in[6];
    const float* b_ih1 = (const float*)d_in[7];
    const float* b_hh1 = (const float*)d_in[8];
    const float* fc_w  = (const float*)d_in[9];
    const float* fc_b  = (const float*)d_in[10];

    float *h1fp, *h2fp, *h2pp;
    unsigned *leafp, *rootp;
    cudaGetSymbolAddress((void**)&h1fp, g_h1f);
    cudaGetSymbolAddress((void**)&h2fp, g_h2f);
    cudaGetSymbolAddress((void**)&h2pp, g_h2p);
    cudaGetSymbolAddress((void**)&leafp, g_leaf);
    cudaGetSymbolAddress((void**)&rootp, g_root);

    static bool attr_set = false;
    if (!attr_set) {
        cudaFuncSetAttribute(k_scan, cudaFuncAttributeMaxDynamicSharedMemorySize,
                             (int)SMEM_BYTES);
        attr_set = true;
    }

    // Deterministic per-call init (memset nodes, not kernels)
    cudaMemsetAsync(h1fp, 0, sizeof(g_h1f), 0);
    cudaMemsetAsync(h2fp, 0, sizeof(g_h2f), 0);
    cudaMemsetAsync(leafp, 0, sizeof(g_leaf), 0);
    cudaMemsetAsync(rootp, 0, sizeof(g_root), 0);

    // One-time transposes: x -> g_xf, W_ih0 -> g_wf
    k_prep<<<2112, 256>>>(x, W_ih0);

    // Persistent fused 2-layer scan (x-GEMM fused; no xp0)
    k_scan<<<GRID, NTHR, SMEM_BYTES>>>(W_hh0, W_ih1, W_hh1,
                                       b_ih0, b_hh0, b_ih1, b_hh1);

    // FC head
    k_fc<<<dim3(1, 4), 256>>>(h2pp, fc_w, fc_b, (float*)d_out);
}

// round 10
// speedup vs baseline: 1.6310x; 1.1395x over previous
#include <cuda_runtime.h>
#include <cstdint>
#include <cstddef>

constexpr int kB = 128, kT = 256, kI = 256, kH = 512, kO = 128;
constexpr int kFH = 4 * kH, kBH = kB * kH;

// Scratch
// x transposed to mma-fragment-interleaved: [t][mcta][kchunk of 64][4096]
__device__ float g_xf[kT][2][4][4096];
// W_ih0 per-ncta slice, frag-interleaved
__device__ float g_wf[64][8192];
// h in frag-interleaved layout, 3-deep ring: [buf][mcta][chunk of 64 k][4096]
// (3 buffers tolerate the <2-iteration skew proven by the counter protocol)
__device__ float g_h1f[3][2][8][4096];
__device__ float g_h2f[3][2][8][4096];
__device__ float g_h2p[kBH];                   // plain final h2 for FC
// Data-flow counters: cnt[it*2+mcta] = #CTAs (of 64 in that half) that stored
// h for timestep-iteration `it`. No grid barrier anywhere.
__device__ unsigned g_cnt1[2 * (kT + 2)];
__device__ unsigned g_cnt2[2 * (kT + 2)];

constexpr int GRID = 128, NTHR = 512;

// SMEM (floats)
constexpr int CEX_LD = 34;
constexpr int SM_WH0 = 0;
constexpr int SM_WI1 = 16384;
constexpr int SM_WH1 = 32768;
constexpr int SM_CEX = 49152;                       // [4][64][34] = 8704
constexpr int SM_B1  = SM_CEX + 4 * 64 * CEX_LD;    // l1 bias sums (32)
constexpr int SM_B2  = SM_B1 + 32;                  // l2 bias sums (32)
constexpr int SM_TOTF = SM_B2 + 32;                 // 57920 fl = 231680 B
constexpr size_t SMEM_BYTES = (size_t)SM_TOTF * sizeof(float);

__device__ __forceinline__ float to_tf32(float x) {
    uint32_t u;
    asm("cvt.rna.tf32.f32 %0, %1;" : "=r"(u) : "f"(x));
    return __uint_as_float(u);
}

__device__ __forceinline__ void mma_tf32(float* d, const uint32_t* a, const uint32_t* b) {
    asm volatile(
        "mma.sync.aligned.m16n8k8.row.col.f32.tf32.tf32.f32 "
        "{%0,%1,%2,%3}, {%4,%5,%6,%7}, {%8,%9}, {%0,%1,%2,%3};\n"
        : "+f"(d[0]), "+f"(d[1]), "+f"(d[2]), "+f"(d[3])
        : "r"(a[0]), "r"(a[1]), "r"(a[2]), "r"(a[3]), "r"(b[0]), "r"(b[1]));
}

__device__ __forceinline__ float sigm(float x) { return 1.0f / (1.0f + expf(-x)); }

// =====================================================================
// One-time transpose: x -> g_xf (frag-interleaved), W_ih0 -> g_wf slices.
// =====================================================================
__global__ void __launch_bounds__(256) k_prep(const float* __restrict__ x,
                                              const float* __restrict__ Wih0)
{
    __shared__ float tile[64][68];   // 272B rows: every row 16B-aligned
    const int tid = threadIdx.x;
    const int u = blockIdx.x;
    if (u < 2048) {
        const int ch = u & 3, mc = (u >> 2) & 1, t = u >> 3;
#pragma unroll
        for (int p = 0; p < 4; ++p) {
            const int v = tid + p * 256;
            const int r = v >> 4, k4 = v & 15;
            const float4 val = __ldg((const float4*)&x[
                (size_t)(mc * 64 + r) * (kT * kI) + (size_t)t * kI + ch * 64 + k4 * 4]);
            *(float4*)&tile[r][k4 * 4] = val;
        }
        __syncthreads();
        float* dst = &g_xf[t][mc][ch][0];
#pragma unroll
        for (int p = 0; p < 4; ++p) {
            const int base = (tid + p * 256) * 4;
            float ov[4];
#pragma unroll
            for (int e = 0; e < 4; ++e) {
                const int idx = base + e;
                const int k8 = idx >> 9, rt = (idx >> 7) & 3;
                const int ln = (idx >> 2) & 31, comp = idx & 3;
                const int r = rt * 16 + ((comp & 1) << 3) + (ln >> 2);
                const int k = k8 * 8 + ((comp >> 1) << 2) + (ln & 3);
                ov[e] = to_tf32(tile[r][k]);
            }
            *(float4*)&dst[base] = make_float4(ov[0], ov[1], ov[2], ov[3]);
        }
    } else {
        const int nc = u - 2048;
        float* dst = &g_wf[nc][0];
#pragma unroll
        for (int p = 0; p < 8; ++p) {
            const int base = (tid + p * 256) * 4;
            float ov[4];
#pragma unroll
            for (int e = 0; e < 4; ++e) {
                const int idx = base + e;
                const int k8 = idx >> 8, g = (idx >> 6) & 3;
                const int ln = (idx >> 1) & 31, c2 = idx & 1;
                const int k = k8 * 8 + (c2 << 2) + (ln & 3);
                const int grow = g * kH + nc * 8 + (ln >> 2);
                ov[e] = to_tf32(Wih0[grow * kI + k]);
            }
            *(float4*)&dst[base] = make_float4(ov[0], ov[1], ov[2], ov[3]);
        }
    }
}

// =====================================================================
// Persistent fused 2-layer LSTM scan, barrier-free (data-flow counters).
// CTA c: mcta=c&1 rows [mcta*64,+64); ncta=c>>1 h-cols [ncta*8,+8).
// 16 warps: kq=w&3 (k-split 4), mw=w>>2, warp tile m16 x n32.
// Iter it: layer-1 step it (wait cnt1[it-1]) + layer-2 step it-1
// (wait cnt2[it-1] before issuing h2 loads). Producers red.release their
// counters right after storing h. 3-deep h ring buffers bound the skew.
// =====================================================================
__global__ void __launch_bounds__(NTHR, 1) k_scan(
    const float* __restrict__ Whh0, const float* __restrict__ Wih1,
    const float* __restrict__ Whh1,
    const float* __restrict__ bih0, const float* __restrict__ bhh0,
    const float* __restrict__ bih1, const float* __restrict__ bhh1)
{
    extern __shared__ float sm[];
    const int tid  = threadIdx.x;
    const int lane = tid & 31;
    const int w    = tid >> 5;
    const int kq   = w & 3;
    const int mw   = w >> 2;
    const int mcta = blockIdx.x & 1;
    const int ncta = blockIdx.x >> 1;
    const int hbase = ncta * 8;
    const int row0  = mcta * 64;

    // ---- Weight slices into SMEM, fragment-interleaved ----
    for (int i = tid; i < 32 * 512; i += NTHR) {
        const int cc = i >> 9, k = i & 511;
        const int grow = (cc >> 3) * kH + hbase + (cc & 7);
        const int idx = (((k >> 3) * 4 + (cc >> 3)) * 32 + (((cc & 7) << 2) | (k & 3))) * 2
                        + ((k >> 2) & 1);
        sm[SM_WH0 + idx] = to_tf32(Whh0[grow * kH + k]);
        sm[SM_WI1 + idx] = to_tf32(Wih1[grow * kH + k]);
        sm[SM_WH1 + idx] = to_tf32(Whh1[grow * kH + k]);
    }
    if (tid < 32) {
        const int grow = (tid >> 3) * kH + hbase + (tid & 7);
        sm[SM_B1 + tid] = bih0[grow] + bhh0[grow];
        sm[SM_B2 + tid] = bih1[grow] + bhh1[grow];
    }
    __syncthreads();

    const int er = tid >> 3;
    const int ej = tid & 7;
    const int hidx = ((((ncta & 7) * 4 + (er >> 4)) * 32 +
                      (((er & 7) << 2) | (ej & 3))) * 4) +
                     ((er >> 3) & 1) + (((ej >> 2) & 1) << 1);
    const int hchunk = ncta >> 3;
    const int foff = (mw * 32 + lane) * 4;
    const float* __restrict__ wfp = &g_wf[ncta][0];

    float c1s = 0.f, c2s = 0.f;

    float4 ring[8];
    float2 wv[3][4];

    auto issue_x = [&](int itx) {
        const float* cbx = &g_xf[itx][mcta][kq][0] + foff;
#pragma unroll
        for (int j = 0; j < 8; ++j)
            ring[j] = __ldcg((const float4*)(cbx + j * 512));
#pragma unroll
        for (int g = 0; g < 3; ++g)
#pragma unroll
            for (int t = 0; t < 4; ++t)
                wv[g][t] = __ldcg((const float2*)(wfp +
                    (((kq * 8 + g) * 4 + t) * 32 + lane) * 2));
    };

    // tid0 acquire-polls counter >= 64, then CTA-wide sync.
    auto wait_cnt = [&](unsigned* cnt) {
        if (tid == 0) {
            unsigned v;
            do {
                asm volatile("ld.acquire.gpu.u32 %0, [%1];"
                             : "=r"(v) : "l"(cnt) : "memory");
                if (v >= 64) break;
                __nanosleep(32);
            } while (true);
        }
        __syncthreads();
    };
    // Pattern: all threads stored -> __syncthreads -> tid0 fence + red.release.
    auto bump_cnt = [&](unsigned* cnt) {
        if (tid == 0) {
            __threadfence();
            asm volatile("red.release.gpu.global.add.u32 [%0], %1;"
                         :: "l"(cnt), "r"(1u) : "memory");
        }
    };

    int b_cur = 0, b_nxt = 1;   // it % 3, (it+1) % 3
    issue_x(0);

    for (int it = 0; it <= kT; ++it) {
        const bool do1 = (it < kT);
        const bool do2 = (it >= 1);
        const float* __restrict__ h1r = &g_h1f[b_cur][mcta][0][0];
        const float* __restrict__ h2r = &g_h2f[b_cur][mcta][0][0];

        const float* cb1a = h1r + (kq * 2 + 0) * 4096 + foff;
        const float* cb1b = h1r + (kq * 2 + 1) * 4096 + foff;
        const float* cb2a = h2r + (kq * 2 + 0) * 4096 + foff;
        const float* cb2b = h2r + (kq * 2 + 1) * 4096 + foff;

        float acc1[4][4], acc2[4][4];
#pragma unroll
        for (int t = 0; t < 4; ++t)
#pragma unroll
            for (int q = 0; q < 4; ++q) { acc1[t][q] = 0.f; acc2[t][q] = 0.f; }

        // h1[it-1] must be fully stored before we issue h1 loads.
        if (it >= 1) wait_cnt(&g_cnt1[(it - 1) * 2 + mcta]);

        if (!do1) {
#pragma unroll
            for (int j = 0; j < 8; ++j)
                ring[j] = __ldcg((const float4*)(cb1a + j * 512));
        }

        // ---- Section X: x @ Wih0 -> acc1; refill ring with h1 chunk A ----
        if (do1) {
#pragma unroll
            for (int j = 0; j < 8; ++j) {
                const float4 af = ring[j];
                ring[j] = __ldcg((const float4*)(cb1a + j * 512));
                uint32_t au[4] = { __float_as_uint(af.x), __float_as_uint(af.y),
                                   __float_as_uint(af.z), __float_as_uint(af.w) };
#pragma unroll
                for (int t = 0; t < 4; ++t) {
                    float2 bb = wv[j % 3][t];
                    uint32_t bu[2] = { __float_as_uint(bb.x), __float_as_uint(bb.y) };
                    mma_tf32(acc1[t], au, bu);
                }
                if (j + 3 < 8) {
#pragma unroll
                    for (int t = 0; t < 4; ++t)
                        wv[j % 3][t] = __ldcg((const float2*)(wfp +
                            (((kq * 8 + j + 3) * 4 + t) * 32 + lane) * 2));
                }
            }
        }

        // ---- Section H1A: consume h1a, refill h1b ----
#pragma unroll
        for (int j = 0; j < 8; ++j) {
            const float4 af = ring[j];
            ring[j] = __ldcg((const float4*)(cb1b + j * 512));
            uint32_t au[4] = { __float_as_uint(af.x), __float_as_uint(af.y),
                               __float_as_uint(af.z), __float_as_uint(af.w) };
            const int k8g = (kq * 2) * 8 + j;
            if (do1) {
#pragma unroll
                for (int t = 0; t < 4; ++t) {
                    const float2 bb = *(const float2*)&sm[SM_WH0 +
                        ((k8g * 4 + t) * 32 + lane) * 2];
                    uint32_t bu[2] = { __float_as_uint(bb.x), __float_as_uint(bb.y) };
                    mma_tf32(acc1[t], au, bu);
                }
            }
            if (do2) {
#pragma unroll
                for (int t = 0; t < 4; ++t) {
                    const float2 bb = *(const float2*)&sm[SM_WI1 +
                        ((k8g * 4 + t) * 32 + lane) * 2];
                    uint32_t bu[2] = { __float_as_uint(bb.x), __float_as_uint(bb.y) };
                    mma_tf32(acc2[t], au, bu);
                }
            }
        }

        // h2[it-2 state] must be stored before issuing h2 loads (first in H1B).
        if (it >= 2) wait_cnt(&g_cnt2[(it - 1) * 2 + mcta]);

        // ---- Section H1B: consume h1b, refill h2a ----
#pragma unroll
        for (int j = 0; j < 8; ++j) {
            const float4 af = ring[j];
            if (do2) ring[j] = __ldcg((const float4*)(cb2a + j * 512));
            uint32_t au[4] = { __float_as_uint(af.x), __float_as_uint(af.y),
                               __float_as_uint(af.z), __float_as_uint(af.w) };
            const int k8g = (kq * 2 + 1) * 8 + j;
            if (do1) {
#pragma unroll
                for (int t = 0; t < 4; ++t) {
                    const float2 bb = *(const float2*)&sm[SM_WH0 +
                        ((k8g * 4 + t) * 32 + lane) * 2];
                    uint32_t bu[2] = { __float_as_uint(bb.x), __float_as_uint(bb.y) };
                    mma_tf32(acc1[t], au, bu);
                }
            }
            if (do2) {
#pragma unroll
                for (int t = 0; t < 4; ++t) {
                    const float2 bb = *(const float2*)&sm[SM_WI1 +
                        ((k8g * 4 + t) * 32 + lane) * 2];
                    uint32_t bu[2] = { __float_as_uint(bb.x), __float_as_uint(bb.y) };
                    mma_tf32(acc2[t], au, bu);
                }
            }
        }

        // ---- Sections H2A/H2B ----
        if (do2) {
#pragma unroll
            for (int j = 0; j < 8; ++j) {
                const float4 af = ring[j];
                ring[j] = __ldcg((const float4*)(cb2b + j * 512));
                uint32_t au[4] = { __float_as_uint(af.x), __float_as_uint(af.y),
                                   __float_as_uint(af.z), __float_as_uint(af.w) };
                const int k8g = (kq * 2) * 8 + j;
#pragma unroll
                for (int t = 0; t < 4; ++t) {
                    const float2 bb = *(const float2*)&sm[SM_WH1 +
                        ((k8g * 4 + t) * 32 + lane) * 2];
                    uint32_t bu[2] = { __float_as_uint(bb.x), __float_as_uint(bb.y) };
                    mma_tf32(acc2[t], au, bu);
                }
            }
#pragma unroll
            for (int j = 0; j < 8; ++j) {
                const float4 af = ring[j];
                uint32_t au[4] = { __float_as_uint(af.x), __float_as_uint(af.y),
                                   __float_as_uint(af.z), __float_as_uint(af.w) };
                const int k8g = (kq * 2 + 1) * 8 + j;
#pragma unroll
                for (int t = 0; t < 4; ++t) {
                    const float2 bb = *(const float2*)&sm[SM_WH1 +
                        ((k8g * 4 + t) * 32 + lane) * 2];
                    uint32_t bu[2] = { __float_as_uint(bb.x), __float_as_uint(bb.y) };
                    mma_tf32(acc2[t], au, bu);
                }
            }
        }

        // Next iteration's x/W loads (static data; no dependency)
        if (it + 1 < kT) issue_x(it + 1);

        // ---- Layer-1 epilogue: reduce, cell update, store h1[it], signal ----
        if (do1) {
            const int r  = mw * 16 + (lane >> 2);
            const int cb = (lane & 3) * 2;
#pragma unroll
            for (int t = 0; t < 4; ++t) {
                float* cx = &sm[SM_CEX + (kq * 64 + r) * CEX_LD + t * 8 + cb];
                *(float2*)cx                = make_float2(acc1[t][0], acc1[t][1]);
                *(float2*)(cx + 8 * CEX_LD) = make_float2(acc1[t][2], acc1[t][3]);
            }
            __syncthreads();
            float pre[4];
#pragma unroll
            for (int g = 0; g < 4; ++g) {
                float s = sm[SM_B1 + g * 8 + ej];
#pragma unroll
                for (int q = 0; q < 4; ++q)
                    s += sm[SM_CEX + (q * 64 + er) * CEX_LD + g * 8 + ej];
                pre[g] = s;
            }
            const float ig = sigm(pre[0]), fg = sigm(pre[1]);
            const float gg = tanhf(pre[2]), og = sigm(pre[3]);
            const float cn = fg * c1s + ig * gg;
            c1s = cn;
            g_h1f[b_nxt][mcta][hchunk][hidx] = to_tf32(og * tanhf(cn));
            __syncthreads();
            bump_cnt(&g_cnt1[it * 2 + mcta]);
        }

        // ---- Layer-2 epilogue ----
        if (do2) {
            const int r  = mw * 16 + (lane >> 2);
            const int cb = (lane & 3) * 2;
#pragma unroll
            for (int t = 0; t < 4; ++t) {
                float* cx = &sm[SM_CEX + (kq * 64 + r) * CEX_LD + t * 8 + cb];
                *(float2*)cx                = make_float2(acc2[t][0], acc2[t][1]);
                *(float2*)(cx + 8 * CEX_LD) = make_float2(acc2[t][2], acc2[t][3]);
            }
            __syncthreads();
            float pre[4];
#pragma unroll
            for (int g = 0; g < 4; ++g) {
                float s = sm[SM_B2 + g * 8 + ej];
#pragma unroll
                for (int q = 0; q < 4; ++q)
                    s += sm[SM_CEX + (q * 64 + er) * CEX_LD + g * 8 + ej];
                pre[g] = s;
            }
            const float ig = sigm(pre[0]), fg = sigm(pre[1]);
            const float gg = tanhf(pre[2]), og = sigm(pre[3]);
            const float cn = fg * c2s + ig * gg;
            c2s = cn;
            const float hv = og * tanhf(cn);
            g_h2f[b_nxt][mcta][hchunk][hidx] = to_tf32(hv);
            if (it == kT) g_h2p[(row0 + er) * kH + hbase + ej] = hv;
            __syncthreads();
            bump_cnt(&g_cnt2[it * 2 + mcta]);
        }

        // advance ring-buffer indices (mod 3)
        b_cur = b_nxt;
        b_nxt = b_nxt + 1;
        if (b_nxt == 3) b_nxt = 0;
    }
}

// =====================================================================
// FC head: out = h2_final @ fc_w^T + fc_b
// =====================================================================
__global__ __launch_bounds__(256) void k_fc(
    const float* __restrict__ A0, const float* __restrict__ W0,
    const float* __restrict__ bias0, float* __restrict__ outp)
{
    __shared__ float Asf[512];
    __shared__ float Bsf[2048];

    const int tid  = threadIdx.x;
    const int lane = tid & 31;
    const int w    = tid >> 5;
    const int mw   = w >> 2;
    const int nw   = w & 3;
    const int mtile = blockIdx.y;

    float acc[4][4];
#pragma unroll
    for (int j = 0; j < 4; j++)
#pragma unroll
        for (int q = 0; q < 4; q++) acc[j][q] = 0.0f;

    const int a_r  = tid >> 3;
    const int a_kk = (tid & 7) * 2;
    const int b_n   = tid >> 1;
    const int b_kk8 = (tid & 1) * 8;

#pragma unroll 1
    for (int kt = 0; kt < kH; kt += 16) {
        {
            const int gm = mtile * 32 + a_r;
            const float2 v = *(const float2*)&A0[(size_t)gm * kH + kt + a_kk];
            const float vv[2] = { v.x, v.y };
#pragma unroll
            for (int e = 0; e < 2; ++e) {
                const int k = a_kk + e;
                const int g = (k >> 3) * 2 + (a_r >> 4);
                const int ln = ((a_r & 7) << 2) | (k & 3);
                const int comp = ((a_r >> 3) & 1) | (((k >> 2) & 1) << 1);
                Asf[(g * 32 + ln) * 4 + comp] = to_tf32(vv[e]);
            }
        }
        {
            const float4* p = (const float4*)&W0[(size_t)b_n * kH + kt + b_kk8];
            const float4 v0 = p[0], v1 = p[1];
            const float vv[8] = { v0.x, v0.y, v0.z, v0.w, v1.x, v1.y, v1.z, v1.w };
#pragma unroll
            for (int e = 0; e < 8; ++e) {
                const int k = b_kk8 + e;
                const int g = (k >> 3) * 16 + (b_n >> 3);
                const int ln = ((b_n & 7) << 2) | (k & 3);
                const int comp = (k >> 2) & 1;
                Bsf[(g * 32 + ln) * 2 + comp] = to_tf32(vv[e]);
            }
        }
        __syncthreads();

#pragma unroll
        for (int k8 = 0; k8 < 2; ++k8) {
            const float4 af = *(const float4*)&Asf[((k8 * 2 + mw) * 32 + lane) * 4];
            uint32_t au[4] = { __float_as_uint(af.x), __float_as_uint(af.y),
                               __float_as_uint(af.z), __float_as_uint(af.w) };
#pragma unroll
            for (int j = 0; j < 4; ++j) {
                const float2 b = *(const float2*)&Bsf[((k8 * 16 + nw * 4 + j) * 32 + lane) * 2];
                uint32_t bu[2] = { __float_as_uint(b.x), __float_as_uint(b.y) };
                mma_tf32(acc[j], au, bu);
            }
        }
        __syncthreads();
    }

    const int gr = mtile * 32 + mw * 16 + (lane >> 2);
    const int cbase = nw * 32 + (lane & 3) * 2;
#pragma unroll
    for (int j = 0; j < 4; j++) {
        const int c0 = cbase + j * 8;
        const float bv0 = bias0[c0];
        const float bv1 = bias0[c0 + 1];
        outp[(size_t)gr * kO + c0]           = acc[j][0] + bv0;
        outp[(size_t)gr * kO + c0 + 1]       = acc[j][1] + bv1;
        outp[(size_t)(gr + 8) * kO + c0]     = acc[j][2] + bv0;
        outp[(size_t)(gr + 8) * kO + c0 + 1] = acc[j][3] + bv1;
    }
}

extern "C" void kernel_launch(void* const* d_in, const int* in_sizes, int n_in,
                              void* d_out, int out_size)
{
    const float* x     = (const float*)d_in[0];
    const float* W_ih0 = (const float*)d_in[1];
    const float* W_hh0 = (const float*)d_in[2];
    const float* b_ih0 = (const float*)d_in[3];
    const float* b_hh0 = (const float*)d_in[4];
    const float* W_ih1 = (const float*)d_in[5];
    const float* W_hh1 = (const float*)d_in[6];
    const float* b_ih1 = (const float*)d_in[7];
    const float* b_hh1 = (const float*)d_in[8];
    const float* fc_w  = (const float*)d_in[9];
    const float* fc_b  = (const float*)d_in[10];

    float *h1fp, *h2fp, *h2pp;
    unsigned *c1p, *c2p;
    cudaGetSymbolAddress((void**)&h1fp, g_h1f);
    cudaGetSymbolAddress((void**)&h2fp, g_h2f);
    cudaGetSymbolAddress((void**)&h2pp, g_h2p);
    cudaGetSymbolAddress((void**)&c1p,  g_cnt1);
    cudaGetSymbolAddress((void**)&c2p,  g_cnt2);

    static bool attr_set = false;
    if (!attr_set) {
        cudaFuncSetAttribute(k_scan, cudaFuncAttributeMaxDynamicSharedMemorySize,
                             (int)SMEM_BYTES);
        attr_set = true;
    }

    // Deterministic per-call init
    cudaMemsetAsync(h1fp, 0, sizeof(g_h1f), 0);
    cudaMemsetAsync(h2fp, 0, sizeof(g_h2f), 0);
    cudaMemsetAsync(c1p,  0, sizeof(g_cnt1), 0);
    cudaMemsetAsync(c2p,  0, sizeof(g_cnt2), 0);

    // One-time transposes: x -> g_xf, W_ih0 -> g_wf
    k_prep<<<2112, 256>>>(x, W_ih0);

    // Persistent fused 2-layer scan (barrier-free, counter-synced)
    k_scan<<<GRID, NTHR, SMEM_BYTES>>>(W_hh0, W_ih1, W_hh1,
                                       b_ih0, b_hh0, b_ih1, b_hh1);

    // FC head
    k_fc<<<dim3(1, 4), 256>>>(h2pp, fc_w, fc_b, (float*)d_out);
}